// round 14
// baseline (speedup 1.0000x reference)
#include <cuda_runtime.h>
#include <cstdint>

// Problem constants (fixed by the dataset)
#define NN 100000
#define NE 1600000
#define F  32

// Scratch (no cudaMalloc allowed) — referenced directly from device code.
// Invariant: g_cnt and g_total are zero at entry to kernel_launch.
// (BSS-zeroed on first call; k_allocproject resets g_cnt after consuming it,
//  k_fill resets g_total after k_allocproject consumed it.)
__device__ int           g_cnt[NN];          // in-degree (excl. self-loop)
__device__ int           g_start[NN];        // packed bin start offsets
__device__ int           g_end[NN];          // packed bin end offsets
__device__ unsigned char g_relpos[NE];       // slot within dst bin (max deg << 255)
__device__ int           g_ebin[NE];         // src ids grouped by dst (packed)
__device__ int           g_total;            // global bin allocator
__device__ float         g_h[(size_t)NN * F];// projected features

// ---------------------------------------------------------------------------
// Kernel 1: histogram of dst; keep returned slot (byte) so fill is atomic-free
// ---------------------------------------------------------------------------
__global__ void k_hist(const int* __restrict__ dst, int e) {
    int i = blockIdx.x * blockDim.x + threadIdx.x;
    if (i < e) {
        int d = __ldg(dst + i);
        g_relpos[i] = (unsigned char)atomicAdd(&g_cnt[d], 1);
    }
}

// ---------------------------------------------------------------------------
// Kernel 2 (fused): packed-bin allocation (warp scan + one global atomic per
// warp) + projection h[v] = (x[v] * rsqrt(deg[v])) @ W^T, chunked accumulators.
// Writes g_start/g_end and RESETS g_cnt (it is the last reader of the count;
// aggregate uses end-start). Reset must NOT live in k_aggregate: tried 3x
// (R8/R11/R12), each time slowed the gather loop 3-12x.
// ---------------------------------------------------------------------------
__global__ void __launch_bounds__(256) k_allocproject(
        const float* __restrict__ x,
        const float* __restrict__ W, int n) {
    __shared__ float sW[F][F];
    for (int i = threadIdx.x; i < F * F; i += blockDim.x)
        sW[i / F][i % F] = W[i];
    __syncthreads();

    int t = blockIdx.x * blockDim.x + threadIdx.x;
    int lane = t & 31;
    int v = t;

    // ---- bin allocation: inclusive warp scan of counts ----
    int c = (v < n) ? g_cnt[v] : 0;
    int inc = c;
#pragma unroll
    for (int off = 1; off < 32; off <<= 1) {
        int tmp = __shfl_up_sync(0xFFFFFFFFu, inc, off);
        if (lane >= off) inc += tmp;
    }
    int excl = inc - c;
    int base = 0;
    if (lane == 31) base = atomicAdd(&g_total, inc);
    base = __shfl_sync(0xFFFFFFFFu, base, 31);
    if (v < n) {
        int s = base + excl;
        g_start[v] = s;
        g_end[v] = s + c;
        g_cnt[v] = 0;            // restore invariant for next launch
    }

    // ---- projection ----
    if (v >= n) return;

    float s = rsqrtf((float)(c + 1));

    float xr[F];
    const float4* xp = reinterpret_cast<const float4*>(x + (size_t)v * F);
#pragma unroll
    for (int i = 0; i < F / 4; i++) {
        float4 q = __ldg(xp + i);
        xr[4 * i + 0] = q.x * s;
        xr[4 * i + 1] = q.y * s;
        xr[4 * i + 2] = q.z * s;
        xr[4 * i + 3] = q.w * s;
    }

    float4* hp = reinterpret_cast<float4*>(g_h + (size_t)v * F);
#pragma unroll 1
    for (int chunk = 0; chunk < 4; chunk++) {
        float acc[8];
#pragma unroll
        for (int o = 0; o < 8; o++) acc[o] = 0.0f;
#pragma unroll
        for (int i = 0; i < F; i++) {
            float xi = xr[i];
#pragma unroll
            for (int o = 0; o < 8; o++)
                acc[o] = fmaf(xi, sW[chunk * 8 + o][i], acc[o]);
        }
        hp[chunk * 2 + 0] = make_float4(acc[0], acc[1], acc[2], acc[3]);
        hp[chunk * 2 + 1] = make_float4(acc[4], acc[5], acc[6], acc[7]);
    }
}

// ---------------------------------------------------------------------------
// Kernel 3: fill packed bins — pure streaming, slot precomputed by k_hist.
// Also restores g_total = 0 (k_allocproject has already consumed it).
// ---------------------------------------------------------------------------
__global__ void k_fill(const int* __restrict__ src,
                       const int* __restrict__ dst, int e) {
    int i = blockIdx.x * blockDim.x + threadIdx.x;
    if (i == 0) g_total = 0;     // restore invariant for next launch
    if (i >= e) return;
    int d = __ldg(dst + i);
    g_ebin[__ldg(g_start + d) + (int)g_relpos[i]] = __ldg(src + i);
}

// ---------------------------------------------------------------------------
// Kernel 4: FULL warp per node gather + fused epilogue. Measured-good
// structure: warp-uniform ebin broadcast loads, one contiguous row per warp,
// unroll 8, __ldg everywhere, READ-ONLY except `out`. Count derived from
// end-start (g_cnt is already reset by this point).
// ---------------------------------------------------------------------------
__global__ void k_aggregate(const float* __restrict__ bias,
                            float* __restrict__ out, int n) {
    int t = blockIdx.x * blockDim.x + threadIdx.x;
    int v = t >> 5;
    int lane = t & 31;
    if (v >= n) return;

    int start = g_start[v];
    int end = g_end[v];
    int cnt = end - start;

    float acc = g_h[(size_t)v * F + lane];   // self-loop contribution

    int i = start;
    for (; i + 8 <= end; i += 8) {
        int s0 = __ldg(g_ebin + i + 0);
        int s1 = __ldg(g_ebin + i + 1);
        int s2 = __ldg(g_ebin + i + 2);
        int s3 = __ldg(g_ebin + i + 3);
        int s4 = __ldg(g_ebin + i + 4);
        int s5 = __ldg(g_ebin + i + 5);
        int s6 = __ldg(g_ebin + i + 6);
        int s7 = __ldg(g_ebin + i + 7);
        float a0 = __ldg(g_h + (size_t)s0 * F + lane);
        float a1 = __ldg(g_h + (size_t)s1 * F + lane);
        float a2 = __ldg(g_h + (size_t)s2 * F + lane);
        float a3 = __ldg(g_h + (size_t)s3 * F + lane);
        float a4 = __ldg(g_h + (size_t)s4 * F + lane);
        float a5 = __ldg(g_h + (size_t)s5 * F + lane);
        float a6 = __ldg(g_h + (size_t)s6 * F + lane);
        float a7 = __ldg(g_h + (size_t)s7 * F + lane);
        acc += ((a0 + a1) + (a2 + a3)) + ((a4 + a5) + (a6 + a7));
    }
    for (; i + 2 <= end; i += 2) {
        int s0 = __ldg(g_ebin + i + 0);
        int s1 = __ldg(g_ebin + i + 1);
        float a0 = __ldg(g_h + (size_t)s0 * F + lane);
        float a1 = __ldg(g_h + (size_t)s1 * F + lane);
        acc += a0 + a1;
    }
    if (i < end) {
        int s = __ldg(g_ebin + i);
        acc += __ldg(g_h + (size_t)s * F + lane);
    }

    float r = rsqrtf((float)(cnt + 1));
    float b = __ldg(bias + lane);
    out[(size_t)v * F + lane] = fmaxf(fmaf(acc, r, b), 0.0f);
}

// ---------------------------------------------------------------------------
// Launch
// Inputs (metadata order): feature [N*32 f32], src [E i32], dst [E i32],
//                          W [32*32 f32], bias [32 f32]
// Output: [N*32] f32
// ---------------------------------------------------------------------------
extern "C" void kernel_launch(void* const* d_in, const int* in_sizes, int n_in,
                              void* d_out, int out_size) {
    const float* feature = (const float*)d_in[0];
    const int*   src     = (const int*)d_in[1];
    const int*   dst     = (const int*)d_in[2];
    const float* W       = (const float*)d_in[3];
    const float* bias    = (const float*)d_in[4];
    float*       out     = (float*)d_out;

    int n = in_sizes[0] / F;   // 100000
    int e = in_sizes[1];       // 1600000

    const int B = 256;

    k_hist<<<(e + B - 1) / B, B>>>(dst, e);
    k_allocproject<<<(n + B - 1) / B, B>>>(feature, W, n);
    k_fill<<<(e + B - 1) / B, B>>>(src, dst, e);

    long long athreads = (long long)n * 32;
    int agg_blocks = (int)((athreads + B - 1) / B);
    k_aggregate<<<agg_blocks, B>>>(bias, out, n);
}

// round 15
// speedup vs baseline: 1.3764x; 1.3764x over previous
#include <cuda_runtime.h>
#include <cstdint>

// Problem constants (fixed by the dataset)
#define NN 100000
#define NE 1600000
#define F  32

// Scratch — layout IDENTICAL to the measured-best R9 kernel (the aggregate
// gather loop is layout-sensitive; R14's extra array between these regressed
// it 2.5x). Do not reorder or insert arrays here.
__device__ int           g_cnt[NN];          // in-degree (excl. self-loop)
__device__ int           g_start[NN];        // packed bin start offsets
__device__ unsigned char g_relpos[NE];       // slot within dst bin (max deg << 255)
__device__ int           g_ebin[NE];         // src ids grouped by dst (packed)
__device__ int           g_total;            // global bin allocator
__device__ float         g_h[(size_t)NN * F];// projected features

// ---------------------------------------------------------------------------
// Kernel 1: zero counters (kept separate: folding resets anywhere near the
// aggregate path regressed 4x in R8/R11/R12/R14)
// ---------------------------------------------------------------------------
__global__ void k_zero(int n) {
    int i = blockIdx.x * blockDim.x + threadIdx.x;
    if (i < n) g_cnt[i] = 0;
    if (i == 0) g_total = 0;
}

// ---------------------------------------------------------------------------
// Kernel 2: histogram of dst; keep returned slot (byte) so fill is atomic-free
// ---------------------------------------------------------------------------
__global__ void k_hist(const int* __restrict__ dst, int e) {
    int i = blockIdx.x * blockDim.x + threadIdx.x;
    if (i < e) {
        int d = __ldg(dst + i);
        g_relpos[i] = (unsigned char)atomicAdd(&g_cnt[d], 1);
    }
}

// ---------------------------------------------------------------------------
// Kernel 3: packed-bin allocation — warp scan + one global atomic per warp.
// ---------------------------------------------------------------------------
__global__ void k_alloc(int n) {
    int t = blockIdx.x * blockDim.x + threadIdx.x;
    int lane = t & 31;
    int c = (t < n) ? g_cnt[t] : 0;

    int inc = c;
#pragma unroll
    for (int off = 1; off < 32; off <<= 1) {
        int tmp = __shfl_up_sync(0xFFFFFFFFu, inc, off);
        if (lane >= off) inc += tmp;
    }
    int excl = inc - c;
    int base = 0;
    if (lane == 31) base = atomicAdd(&g_total, inc);
    base = __shfl_sync(0xFFFFFFFFu, base, 31);
    if (t < n) g_start[t] = base + excl;
}

// ---------------------------------------------------------------------------
// Kernel 4 (heterogeneous blocks): first nproj blocks run the PROJECTION
// (compute-heavy), remaining blocks run the bin FILL (memory-heavy). The two
// are independent (project: g_cnt,x,W -> g_h; fill: g_start,g_relpos,src,dst
// -> g_ebin), so they overlap inside one launch — no streams needed.
// ---------------------------------------------------------------------------
__global__ void __launch_bounds__(256) k_projfill(
        const float* __restrict__ x,
        const float* __restrict__ W,
        const int* __restrict__ src,
        const int* __restrict__ dst,
        int n, int e, int nproj) {
    if ((int)blockIdx.x < nproj) {
        // ---- projection: h[v] = (x[v] * rsqrt(deg[v])) @ W^T ----
        __shared__ float sW[F][F];
        for (int i = threadIdx.x; i < F * F; i += blockDim.x)
            sW[i / F][i % F] = W[i];
        __syncthreads();

        int v = blockIdx.x * blockDim.x + threadIdx.x;
        if (v >= n) return;

        float s = rsqrtf((float)(g_cnt[v] + 1));

        float xr[F];
        const float4* xp = reinterpret_cast<const float4*>(x + (size_t)v * F);
#pragma unroll
        for (int i = 0; i < F / 4; i++) {
            float4 q = __ldg(xp + i);
            xr[4 * i + 0] = q.x * s;
            xr[4 * i + 1] = q.y * s;
            xr[4 * i + 2] = q.z * s;
            xr[4 * i + 3] = q.w * s;
        }

        float4* hp = reinterpret_cast<float4*>(g_h + (size_t)v * F);
#pragma unroll 1
        for (int chunk = 0; chunk < 4; chunk++) {
            float acc[8];
#pragma unroll
            for (int o = 0; o < 8; o++) acc[o] = 0.0f;
#pragma unroll
            for (int i = 0; i < F; i++) {
                float xi = xr[i];
#pragma unroll
                for (int o = 0; o < 8; o++)
                    acc[o] = fmaf(xi, sW[chunk * 8 + o][i], acc[o]);
            }
            hp[chunk * 2 + 0] = make_float4(acc[0], acc[1], acc[2], acc[3]);
            hp[chunk * 2 + 1] = make_float4(acc[4], acc[5], acc[6], acc[7]);
        }
    } else {
        // ---- fill: ebin[start[dst] + relpos] = src ----
        int i = (blockIdx.x - nproj) * blockDim.x + threadIdx.x;
        if (i >= e) return;
        int d = __ldg(dst + i);
        g_ebin[__ldg(g_start + d) + (int)g_relpos[i]] = __ldg(src + i);
    }
}

// ---------------------------------------------------------------------------
// Kernel 5: FULL warp per node gather + fused epilogue. BYTE-IDENTICAL to the
// measured-best R9 aggregate: warp-uniform ebin broadcast loads, unroll 8,
// __ldg everywhere, reads g_start+g_cnt, READ-ONLY except `out`.
// ---------------------------------------------------------------------------
__global__ void k_aggregate(const float* __restrict__ bias,
                            float* __restrict__ out, int n) {
    int t = blockIdx.x * blockDim.x + threadIdx.x;
    int v = t >> 5;
    int lane = t & 31;
    if (v >= n) return;

    int start = g_start[v];
    int cnt = g_cnt[v];
    int end = start + cnt;

    float acc = g_h[(size_t)v * F + lane];   // self-loop contribution

    int i = start;
    for (; i + 8 <= end; i += 8) {
        int s0 = __ldg(g_ebin + i + 0);
        int s1 = __ldg(g_ebin + i + 1);
        int s2 = __ldg(g_ebin + i + 2);
        int s3 = __ldg(g_ebin + i + 3);
        int s4 = __ldg(g_ebin + i + 4);
        int s5 = __ldg(g_ebin + i + 5);
        int s6 = __ldg(g_ebin + i + 6);
        int s7 = __ldg(g_ebin + i + 7);
        float a0 = __ldg(g_h + (size_t)s0 * F + lane);
        float a1 = __ldg(g_h + (size_t)s1 * F + lane);
        float a2 = __ldg(g_h + (size_t)s2 * F + lane);
        float a3 = __ldg(g_h + (size_t)s3 * F + lane);
        float a4 = __ldg(g_h + (size_t)s4 * F + lane);
        float a5 = __ldg(g_h + (size_t)s5 * F + lane);
        float a6 = __ldg(g_h + (size_t)s6 * F + lane);
        float a7 = __ldg(g_h + (size_t)s7 * F + lane);
        acc += ((a0 + a1) + (a2 + a3)) + ((a4 + a5) + (a6 + a7));
    }
    for (; i + 2 <= end; i += 2) {
        int s0 = __ldg(g_ebin + i + 0);
        int s1 = __ldg(g_ebin + i + 1);
        float a0 = __ldg(g_h + (size_t)s0 * F + lane);
        float a1 = __ldg(g_h + (size_t)s1 * F + lane);
        acc += a0 + a1;
    }
    if (i < end) {
        int s = __ldg(g_ebin + i);
        acc += __ldg(g_h + (size_t)s * F + lane);
    }

    float r = rsqrtf((float)(cnt + 1));
    float b = __ldg(bias + lane);
    out[(size_t)v * F + lane] = fmaxf(fmaf(acc, r, b), 0.0f);
}

// ---------------------------------------------------------------------------
// Launch
// Inputs (metadata order): feature [N*32 f32], src [E i32], dst [E i32],
//                          W [32*32 f32], bias [32 f32]
// Output: [N*32] f32
// ---------------------------------------------------------------------------
extern "C" void kernel_launch(void* const* d_in, const int* in_sizes, int n_in,
                              void* d_out, int out_size) {
    const float* feature = (const float*)d_in[0];
    const int*   src     = (const int*)d_in[1];
    const int*   dst     = (const int*)d_in[2];
    const float* W       = (const float*)d_in[3];
    const float* bias    = (const float*)d_in[4];
    float*       out     = (float*)d_out;

    int n = in_sizes[0] / F;   // 100000
    int e = in_sizes[1];       // 1600000

    const int B = 256;

    k_zero<<<(n + B - 1) / B, B>>>(n);
    k_hist<<<(e + B - 1) / B, B>>>(dst, e);
    k_alloc<<<(n + B - 1) / B, B>>>(n);

    int nproj = (n + B - 1) / B;           // 391 projection blocks
    int nfill = (e + B - 1) / B;           // 6250 fill blocks
    k_projfill<<<nproj + nfill, B>>>(feature, W, src, dst, n, e, nproj);

    long long athreads = (long long)n * 32;
    int agg_blocks = (int)((athreads + B - 1) / B);
    k_aggregate<<<agg_blocks, B>>>(bias, out, n);
}